// round 1
// baseline (speedup 1.0000x reference)
#include <cuda_runtime.h>

// Problem constants: B=4, H=256, W=256
#define BHW   262144
#define IMG   65536
#define HW_MASK 65535
#define W_MASK  255
#define NBLK  1024
#define NTHR  256
#define MAXBLKS 512

// ---- persistent device state (no allocation allowed) ----
__device__ float2 g_musig[2][BHW];   // (mu, sigma), ping-pong
__device__ float2 g_rou[2][BHW];     // (rou0, rou1), ping-pong
__device__ float4 g_v[BHW];          // momentum (dmu, dsigma, drou0, drou1)
__device__ float2 g_a1c0[BHW];       // (2*uw1, uw2*y) precomputed
__device__ float  g_blockmax[MAXBLKS];
__device__ float  g_denom;           // max(ew)*1.01 + 1.0

// ---------------- global max of edge_weight ----------------
__global__ __launch_bounds__(256) void ew_max_kernel(const float* __restrict__ ew, int n) {
    float m = -3.4e38f;
    for (int idx = blockIdx.x * blockDim.x + threadIdx.x; idx < n;
         idx += gridDim.x * blockDim.x)
        m = fmaxf(m, ew[idx]);
    #pragma unroll
    for (int o = 16; o; o >>= 1) m = fmaxf(m, __shfl_xor_sync(0xFFFFFFFFu, m, o));
    __shared__ float sm[8];
    if ((threadIdx.x & 31) == 0) sm[threadIdx.x >> 5] = m;
    __syncthreads();
    if (threadIdx.x < 8) {
        float mm = sm[threadIdx.x];
        #pragma unroll
        for (int o = 4; o; o >>= 1) mm = fmaxf(mm, __shfl_xor_sync(0xFFu, mm, o));
        if (threadIdx.x == 0) g_blockmax[blockIdx.x] = mm;
    }
}

__global__ __launch_bounds__(512) void ew_max_final_kernel() {
    float m = g_blockmax[threadIdx.x];
    #pragma unroll
    for (int o = 16; o; o >>= 1) m = fmaxf(m, __shfl_xor_sync(0xFFFFFFFFu, m, o));
    __shared__ float sm[16];
    if ((threadIdx.x & 31) == 0) sm[threadIdx.x >> 5] = m;
    __syncthreads();
    if (threadIdx.x < 16) {
        float mm = sm[threadIdx.x];
        #pragma unroll
        for (int o = 8; o; o >>= 1) mm = fmaxf(mm, __shfl_xor_sync(0xFFFFu, mm, o));
        if (threadIdx.x == 0) g_denom = mm * 1.01f + 1.0f;
    }
}

// ---------------- state init ----------------
__global__ __launch_bounds__(256) void init_kernel(const float* __restrict__ y,
                                                   const float2* __restrict__ ew2,
                                                   const float2* __restrict__ un2) {
    const int p = blockIdx.x * 256 + threadIdx.x;
    const float denom = g_denom;
    float2 ms;
    ms.x = y[p];
    ms.y = 1.0f;
    float2 e = ew2[p];
    float2 r;
    r.x = e.x / denom;
    r.y = e.y / denom;
    float2 u = un2[p];
    float2 ac;
    ac.x = 2.0f * u.x;      // 2*uw1
    ac.y = u.y * ms.x;      // uw2 * y
    g_musig[0][p] = ms;
    g_rou[0][p]   = r;
    g_a1c0[p]     = ac;
    g_v[p] = make_float4(0.f, 0.f, 0.f, 0.f);
}

// ---------------- one optimization step (closed-form Gaussian moments) ----------------
__global__ __launch_bounds__(256) void iter_kernel(const float2* __restrict__ ew2,
                                                   int t, float* __restrict__ out) {
    const int p = blockIdx.x * 256 + threadIdx.x;
    const int s = t & 1;       // read buffer
    const int d = s ^ 1;       // write buffer
    const int base = p & ~HW_MASK;       // image base
    const int i    = p &  HW_MASK;       // h*256 + w
    const int row  = i & ~W_MASK;
    const int pd = base | ((i + 256)   & HW_MASK);          // (h+1, w)
    const int pu = base | ((i + 65280) & HW_MASK);          // (h-1, w)
    const int pr = base | row | ((i + 1)   & W_MASK);       // (h, w+1)
    const int pl = base | row | ((i + 255) & W_MASK);       // (h, w-1)

    const float2 ms  = g_musig[s][p];
    const float2 msd = g_musig[s][pd];
    const float2 msr = g_musig[s][pr];
    const float2 msu = g_musig[s][pu];
    const float2 msl = g_musig[s][pl];
    const float2 r   = g_rou[s][p];
    const float  ru0 = g_rou[s][pu].x;
    const float  rl1 = g_rou[s][pl].y;
    const float2 e   = ew2[p];
    const float  eu0 = ew2[pu].x;
    const float  el1 = ew2[pl].y;
    const float2 ac  = g_a1c0[p];
    float4 vv = g_v[p];

    // Exact Gauss-Hermite quadrature values (quadrature is exact for these
    // polynomial integrands; all log/normalizer terms integrate to zero):
    //   dmu    = 2*uw1*mu + uw2*y + sum_d ew_d*mu_nbr + incoming ew*mu from up/left
    //   dsigma = 2*uw1*sigma + sum_d ew_d*rou_d*sigma_nbr + incoming
    //   drou_d = ew_d*sigma*sigma_nbr
    float dmu = fmaf(ac.x, ms.x, ac.y);
    dmu = fmaf(e.x,  msd.x, dmu);
    dmu = fmaf(e.y,  msr.x, dmu);
    dmu = fmaf(eu0,  msu.x, dmu);
    dmu = fmaf(el1,  msl.x, dmu);

    float dsig = ac.x * ms.y;
    dsig = fmaf(e.x * r.x,  msd.y, dsig);
    dsig = fmaf(e.y * r.y,  msr.y, dsig);
    dsig = fmaf(eu0 * ru0,  msu.y, dsig);
    dsig = fmaf(el1 * rl1,  msl.y, dsig);

    const float dr0 = e.x * ms.y * msd.y;
    const float dr1 = e.y * ms.y * msr.y;

    // momentum: v = 0.7*v + 0.01*grad
    vv.x = fmaf(0.7f, vv.x, 0.01f * dmu);
    vv.y = fmaf(0.7f, vv.y, 0.01f * dsig);
    vv.z = fmaf(0.7f, vv.z, 0.01f * dr0);
    vv.w = fmaf(0.7f, vv.w, 0.01f * dr1);

    float2 nms, nr;
    nms.x = fminf(fmaxf(ms.x + vv.x, 0.0f),   63.0f);
    nms.y = fminf(fmaxf(ms.y + vv.y, 0.001f), 50.0f);
    nr.x  = fminf(fmaxf(r.x  + vv.z, -0.99f), 0.99f);
    nr.y  = fminf(fmaxf(r.y  + vv.w, -0.99f), 0.99f);

    g_musig[d][p] = nms;
    g_rou[d][p]   = nr;
    g_v[p]        = vv;
    if (out) out[p] = nms.x;
}

// ---------------- launch ----------------
extern "C" void kernel_launch(void* const* d_in, const int* in_sizes, int n_in,
                              void* d_out, int out_size) {
    const float* y  = (const float*)d_in[0];
    const float* ew = (const float*)d_in[1];
    const float* un = (const float*)d_in[2];
    float* out = (float*)d_out;

    ew_max_kernel<<<MAXBLKS, 256>>>(ew, in_sizes[1]);
    ew_max_final_kernel<<<1, 512>>>();
    init_kernel<<<NBLK, NTHR>>>(y, (const float2*)ew, (const float2*)un);
    for (int t = 0; t < 100; ++t) {
        iter_kernel<<<NBLK, NTHR>>>((const float2*)ew, t,
                                    (t == 99) ? out : (float*)nullptr);
    }
}

// round 2
// speedup vs baseline: 1.5137x; 1.5137x over previous
#include <cuda_runtime.h>

// Problem constants: B=4, H=256, W=256
#define BHW     262144
#define HW_MASK 65535
#define W_MASK  255
#define NBLK    1024
#define NTHR    256
#define MAXBLKS 512

// ---- persistent device state (no allocation allowed) ----
// Only mu matters for the output: dmu depends solely on the mu field and
// per-pixel constants. sigma/rou/momentum-yzw are decoupled and dropped.
__device__ float  g_mu[2][BHW];      // mu, ping-pong
__device__ float  g_vx[BHW];         // momentum for mu only
__device__ float4 g_c[BHW];          // (ex, ey, eu0, el1): own down/right edge
                                     //  weights + incoming up/left weights
__device__ float2 g_ac[BHW];         // (2*uw1, uw2*y)
__device__ float  g_blockmax[MAXBLKS];
__device__ float  g_denom;           // max(ew)*1.01 + 1.0 (kept for parity; unused by mu path)

// ---------------- global max of edge_weight (cheap, once per replay) -------
__global__ __launch_bounds__(256) void ew_max_kernel(const float* __restrict__ ew, int n) {
    float m = -3.4e38f;
    for (int idx = blockIdx.x * blockDim.x + threadIdx.x; idx < n;
         idx += gridDim.x * blockDim.x)
        m = fmaxf(m, ew[idx]);
    #pragma unroll
    for (int o = 16; o; o >>= 1) m = fmaxf(m, __shfl_xor_sync(0xFFFFFFFFu, m, o));
    __shared__ float sm[8];
    if ((threadIdx.x & 31) == 0) sm[threadIdx.x >> 5] = m;
    __syncthreads();
    if (threadIdx.x < 8) {
        float mm = sm[threadIdx.x];
        #pragma unroll
        for (int o = 4; o; o >>= 1) mm = fmaxf(mm, __shfl_xor_sync(0xFFu, mm, o));
        if (threadIdx.x == 0) g_blockmax[blockIdx.x] = mm;
    }
}

__global__ __launch_bounds__(512) void ew_max_final_kernel() {
    float m = g_blockmax[threadIdx.x];
    #pragma unroll
    for (int o = 16; o; o >>= 1) m = fmaxf(m, __shfl_xor_sync(0xFFFFFFFFu, m, o));
    __shared__ float sm[16];
    if ((threadIdx.x & 31) == 0) sm[threadIdx.x >> 5] = m;
    __syncthreads();
    if (threadIdx.x < 16) {
        float mm = sm[threadIdx.x];
        #pragma unroll
        for (int o = 8; o; o >>= 1) mm = fmaxf(mm, __shfl_xor_sync(0xFFFFu, mm, o));
        if (threadIdx.x == 0) g_denom = mm * 1.01f + 1.0f;
    }
}

// ---------------- init: pack per-pixel constants ----------------
__global__ __launch_bounds__(256) void init_kernel(const float* __restrict__ y,
                                                   const float2* __restrict__ ew2,
                                                   const float2* __restrict__ un2) {
    const int p = blockIdx.x * 256 + threadIdx.x;
    const int base = p & ~HW_MASK;
    const int i    = p &  HW_MASK;
    const int row  = i & ~W_MASK;
    const int pu = base | ((i + 65280) & HW_MASK);      // (h-1, w)
    const int pl = base | row | ((i + 255) & W_MASK);   // (h, w-1)

    const float yv = y[p];
    const float2 e  = ew2[p];
    const float  eu = ew2[pu].x;
    const float  el = ew2[pl].y;
    const float2 u  = un2[p];

    g_mu[0][p] = yv;
    g_vx[p]    = 0.0f;
    g_c[p]     = make_float4(e.x, e.y, eu, el);
    g_ac[p]    = make_float2(2.0f * u.x, u.y * yv);
}

// ---------------- one optimization step (mu subsystem only) ----------------
__global__ __launch_bounds__(256) void iter_kernel(int t, float* __restrict__ out) {
    const int p = blockIdx.x * 256 + threadIdx.x;
    const int s = t & 1;
    const int d = s ^ 1;
    const int base = p & ~HW_MASK;
    const int i    = p &  HW_MASK;
    const int row  = i & ~W_MASK;
    const int pd = base | ((i + 256)   & HW_MASK);
    const int pu = base | ((i + 65280) & HW_MASK);
    const int pr = base | row | ((i + 1)   & W_MASK);
    const int pl = base | row | ((i + 255) & W_MASK);

    const float mu  = g_mu[s][p];
    const float mud = g_mu[s][pd];
    const float mur = g_mu[s][pr];
    const float muu = g_mu[s][pu];
    const float mul = g_mu[s][pl];
    const float4 c  = g_c[p];
    const float2 ac = g_ac[p];
    float v = g_vx[p];

    float dmu = fmaf(ac.x, mu, ac.y);
    dmu = fmaf(c.x, mud, dmu);
    dmu = fmaf(c.y, mur, dmu);
    dmu = fmaf(c.z, muu, dmu);
    dmu = fmaf(c.w, mul, dmu);

    v = fmaf(0.7f, v, 0.01f * dmu);
    const float nmu = fminf(fmaxf(mu + v, 0.0f), 63.0f);

    g_mu[d][p] = nmu;
    g_vx[p]    = v;
    if (out) out[p] = nmu;
}

// ---------------- launch ----------------
extern "C" void kernel_launch(void* const* d_in, const int* in_sizes, int n_in,
                              void* d_out, int out_size) {
    const float* y  = (const float*)d_in[0];
    const float* ew = (const float*)d_in[1];
    const float* un = (const float*)d_in[2];
    float* out = (float*)d_out;

    ew_max_kernel<<<MAXBLKS, 256>>>(ew, in_sizes[1]);
    ew_max_final_kernel<<<1, 512>>>();
    init_kernel<<<NBLK, NTHR>>>(y, (const float2*)ew, (const float2*)un);
    for (int t = 0; t < 100; ++t) {
        iter_kernel<<<NBLK, NTHR>>>(t, (t == 99) ? out : (float*)nullptr);
    }
}

// round 3
// speedup vs baseline: 3.0650x; 2.0249x over previous
#include <cuda_runtime.h>

// Problem constants: B=4, H=256, W=256. Torus stencil, mu-subsystem only.
#define BHW     262144
#define HW_MASK 65535
#define W_MASK  255

// Temporal tiling: 32x32 tile, T=5 fused iterations, region 42x42.
#define TILE    32
#define T       5
#define RSIDE   42          // TILE + 2*T
#define RC      1764        // RSIDE*RSIDE
#define RLAST   1722        // RC - RSIDE
#define SLOTS   7           // ceil(RC/256)
#define NLAUNCH 20          // 100 / T

// ---- persistent device state (no allocation allowed) ----
__device__ float  g_mu[2][BHW];   // mu ping-pong (across launches)
__device__ float  g_v [2][BHW];   // momentum ping-pong (halo cells need old v)
__device__ float4 g_c [BHW];      // (ex, ey, eu0, el1)
__device__ float2 g_ac[BHW];      // (2*uw1, uw2*y)

// ---------------- init: pack per-pixel constants ----------------
__global__ __launch_bounds__(256) void init_kernel(const float* __restrict__ y,
                                                   const float2* __restrict__ ew2,
                                                   const float2* __restrict__ un2) {
    const int p = blockIdx.x * 256 + threadIdx.x;
    const int base = p & ~HW_MASK;
    const int i    = p &  HW_MASK;
    const int row  = i & ~W_MASK;
    const int pu = base | ((i + 65280) & HW_MASK);      // (h-1, w)
    const int pl = base | row | ((i + 255) & W_MASK);   // (h, w-1)

    const float yv = y[p];
    const float2 e  = ew2[p];
    const float  eu = ew2[pu].x;
    const float  el = ew2[pl].y;
    const float2 u  = un2[p];

    g_mu[0][p] = yv;
    g_v [0][p] = 0.0f;
    g_c [p]    = make_float4(e.x, e.y, eu, el);
    g_ac[p]    = make_float2(2.0f * u.x, u.y * yv);
}

// ---------------- T fused steps per launch, halo recompute ----------------
__global__ __launch_bounds__(256) void fused_kernel(int s, float* __restrict__ out) {
    __shared__ float sm[2][RC];

    const int tid = threadIdx.x;
    const int blk = blockIdx.x;                  // 256 blocks: 4 imgs x 8x8 tiles
    const int base = (blk >> 6) << 16;           // image base
    const int th = (blk >> 3) & 7;
    const int tw = blk & 7;
    const int h0 = th * TILE - T;                // region origin (may be negative; &255 wraps)
    const int w0 = tw * TILE - T;

    float4 c4[SLOTS];
    float2 ac2[SLOTS];
    float  vv[SLOTS], mm[SLOTS];
    int    col[SLOTS];

    // Load region state + constants into registers / smem.
    #pragma unroll
    for (int k = 0; k < SLOTS; ++k) {
        const int idx = tid + k * 256;
        if (idx < RC) {
            const int r  = idx / RSIDE;
            const int cc = idx - r * RSIDE;
            col[k] = cc;
            const int p = base + (((h0 + r) & 255) << 8) + ((w0 + cc) & 255);
            c4[k]  = g_c[p];
            ac2[k] = g_ac[p];
            vv[k]  = g_v[s][p];
            mm[k]  = g_mu[s][p];
            sm[0][idx] = mm[k];
        }
    }
    __syncthreads();

    // T local iterations; arithmetic order identical to the flat kernel.
    int cur = 0;
    #pragma unroll
    for (int it = 0; it < T; ++it) {
        #pragma unroll
        for (int k = 0; k < SLOTS; ++k) {
            const int idx = tid + k * 256;
            if (idx < RC) {
                const int iu = (idx >= RSIDE) ? idx - RSIDE : idx;
                const int id = (idx <  RLAST) ? idx + RSIDE : idx;
                const int il = (col[k] > 0)        ? idx - 1 : idx;
                const int ir = (col[k] < RSIDE-1)  ? idx + 1 : idx;

                float dmu = fmaf(ac2[k].x, mm[k], ac2[k].y);
                dmu = fmaf(c4[k].x, sm[cur][id], dmu);
                dmu = fmaf(c4[k].y, sm[cur][ir], dmu);
                dmu = fmaf(c4[k].z, sm[cur][iu], dmu);
                dmu = fmaf(c4[k].w, sm[cur][il], dmu);

                vv[k] = fmaf(0.7f, vv[k], 0.01f * dmu);
                mm[k] = fminf(fmaxf(mm[k] + vv[k], 0.0f), 63.0f);
                sm[cur ^ 1][idx] = mm[k];
            }
        }
        __syncthreads();
        cur ^= 1;
    }

    // Write back the exact interior tile (distance >= T from region edge).
    #pragma unroll
    for (int k = 0; k < SLOTS; ++k) {
        const int idx = tid + k * 256;
        if (idx < RC) {
            const int r  = idx / RSIDE;
            const int cc = col[k];
            if (r >= T && r < T + TILE && cc >= T && cc < T + TILE) {
                const int p = base + (((h0 + r) & 255) << 8) + ((w0 + cc) & 255);
                g_mu[s ^ 1][p] = mm[k];
                g_v [s ^ 1][p] = vv[k];
                if (out) out[p] = mm[k];
            }
        }
    }
}

// ---------------- launch ----------------
extern "C" void kernel_launch(void* const* d_in, const int* in_sizes, int n_in,
                              void* d_out, int out_size) {
    const float* y  = (const float*)d_in[0];
    const float* ew = (const float*)d_in[1];
    const float* un = (const float*)d_in[2];
    float* out = (float*)d_out;

    init_kernel<<<1024, 256>>>(y, (const float2*)ew, (const float2*)un);
    for (int t = 0; t < NLAUNCH; ++t) {
        fused_kernel<<<256, 256>>>(t & 1, (t == NLAUNCH - 1) ? out : (float*)nullptr);
    }
}